// round 1
// baseline (speedup 1.0000x reference)
#include <cuda_runtime.h>
#include <cuda_bf16.h>
#include <cstdint>

// Problem constants (fixed by the dataset)
constexpr int NN = 100000;    // nodes
constexpr int NE = 3200000;   // edges
constexpr int CIN = 512;
constexpr int CH  = 40;
constexpr int COUT = 20;

// Scratch (static __device__ globals: allocation-free per harness rules)
__device__ float g_h1[(size_t)NN * CH];    // hs1 = dinv * (x@W1)   (message values layer 1)
__device__ float g_acc1[(size_t)NN * CH];  // accumulator layer 1 (init = self-loop term)
__device__ float g_h2[(size_t)NN * COUT];  // hs2 = dinv * (relu(...)@W2)
__device__ float g_acc2[(size_t)NN * COUT];
__device__ float g_dinv[NN];
__device__ int   g_deg[NN];

// ---------------------------------------------------------------------------
// helpers
// ---------------------------------------------------------------------------
__device__ __forceinline__ unsigned long long ffma2(unsigned long long a,
                                                    unsigned long long b,
                                                    unsigned long long c) {
    unsigned long long d;
    asm("fma.rn.f32x2 %0, %1, %2, %3;" : "=l"(d) : "l"(a), "l"(b), "l"(c));
    return d;
}

__device__ __forceinline__ void red_add_v4(float* p, float4 v) {
    asm volatile("red.global.add.v4.f32 [%0], {%1, %2, %3, %4};"
                 :: "l"(p), "f"(v.x), "f"(v.y), "f"(v.z), "f"(v.w)
                 : "memory");
}

// ---------------------------------------------------------------------------
// degree / dinv
// ---------------------------------------------------------------------------
__global__ void k_deg_init() {
    int i = blockIdx.x * 256 + threadIdx.x;
    if (i < NN) g_deg[i] = 1;  // self-loop
}

__global__ void k_deg_count(const int* __restrict__ ei) {
    int e = blockIdx.x * 256 + threadIdx.x;
    if (e < NE) atomicAdd(&g_deg[ei[NE + e]], 1);
}

__global__ void k_dinv() {
    int i = blockIdx.x * 256 + threadIdx.x;
    if (i < NN) g_dinv[i] = rsqrtf((float)g_deg[i]);
}

// ---------------------------------------------------------------------------
// GEMM1: hs1 = dinv * (x @ W1).  M=100000, K=512, N=40, fp32 via f32x2.
// Block = 128 threads, 128 rows. Thread: 8 rows (4 packed pairs) x 5 cols.
// ---------------------------------------------------------------------------
__global__ __launch_bounds__(128) void k_gemm1(const float* __restrict__ x,
                                               const float* __restrict__ W1) {
    __shared__ __align__(16) float xs[16 * 130];  // [k][row], pad 130
    __shared__ __align__(16) float wd[16 * 82];   // [k][2*c] duplicated pairs, pad 82

    const int tid = threadIdx.x;
    const int ct = tid & 7;    // col group: cols ct*5 .. ct*5+4
    const int rp = tid >> 3;   // row group: rows rp*8 .. rp*8+7 (4 pairs)
    const int row_base = blockIdx.x * 128;

    unsigned long long acc[4][5];
#pragma unroll
    for (int i = 0; i < 4; i++)
#pragma unroll
        for (int j = 0; j < 5; j++) acc[i][j] = 0ull;

    for (int kt = 0; kt < CIN; kt += 16) {
        // stage x tile [128 rows][16 k], transposed into xs[k][row]
#pragma unroll
        for (int i = 0; i < 4; i++) {
            int idx = tid + 128 * i;
            int row = idx >> 2;
            int kq = idx & 3;
            int gr = row_base + row;
            float4 v = make_float4(0.f, 0.f, 0.f, 0.f);
            if (gr < NN)
                v = *(const float4*)&x[(size_t)gr * CIN + kt + kq * 4];
            xs[(kq * 4 + 0) * 130 + row] = v.x;
            xs[(kq * 4 + 1) * 130 + row] = v.y;
            xs[(kq * 4 + 2) * 130 + row] = v.z;
            xs[(kq * 4 + 3) * 130 + row] = v.w;
        }
        // stage W tile [16][40] as duplicated float2
#pragma unroll
        for (int i = 0; i < 5; i++) {
            int idx = tid + 128 * i;
            if (idx < 640) {
                int k = idx / 40;
                int c = idx - k * 40;
                float w = W1[(size_t)(kt + k) * CH + c];
                *(float2*)&wd[k * 82 + 2 * c] = make_float2(w, w);
            }
        }
        __syncthreads();

#pragma unroll
        for (int k = 0; k < 16; k++) {
            const unsigned long long* xr =
                (const unsigned long long*)&xs[k * 130 + rp * 8];
            const unsigned long long* wr =
                (const unsigned long long*)&wd[k * 82 + ct * 10];
            unsigned long long xv[4], wv[5];
#pragma unroll
            for (int i = 0; i < 4; i++) xv[i] = xr[i];
#pragma unroll
            for (int j = 0; j < 5; j++) wv[j] = wr[j];
#pragma unroll
            for (int i = 0; i < 4; i++)
#pragma unroll
                for (int j = 0; j < 5; j++)
                    acc[i][j] = ffma2(xv[i], wv[j], acc[i][j]);
        }
        __syncthreads();
    }

    // epilogue: scale by dinv, write message buffer + accumulator (self-loop init)
#pragma unroll
    for (int i = 0; i < 4; i++) {
        int r0 = row_base + rp * 8 + 2 * i;
        int r1 = r0 + 1;
        if (r0 < NN) {
            float d0 = g_dinv[r0];
            float d1 = (r1 < NN) ? g_dinv[r1] : 0.f;
#pragma unroll
            for (int j = 0; j < 5; j++) {
                unsigned long long a = acc[i][j];
                float lo = __uint_as_float((unsigned)a);
                float hi = __uint_as_float((unsigned)(a >> 32));
                int c = ct * 5 + j;
                float v0 = d0 * lo;
                g_h1[(size_t)r0 * CH + c] = v0;
                g_acc1[(size_t)r0 * CH + c] = v0;
                if (r1 < NN) {
                    float v1 = d1 * hi;
                    g_h1[(size_t)r1 * CH + c] = v1;
                    g_acc1[(size_t)r1 * CH + c] = v1;
                }
            }
        }
    }
}

// ---------------------------------------------------------------------------
// Aggregation layer 1: 10 threads per edge, float4 gather + vectored red
// ---------------------------------------------------------------------------
__global__ void k_agg1(const int* __restrict__ ei) {
    unsigned t = blockIdx.x * 256u + threadIdx.x;
    unsigned e = t / 10u;
    if (e >= (unsigned)NE) return;
    unsigned j = t - e * 10u;
    int s = ei[e];
    int d = ei[NE + e];
    float4 v = *(const float4*)&g_h1[(size_t)s * CH + j * 4];
    red_add_v4(&g_acc1[(size_t)d * CH + j * 4], v);
}

// ---------------------------------------------------------------------------
// Layer-1 finish + GEMM2: r = relu(dinv*acc1 + b1); hs2 = dinv * (r @ W2)
// ---------------------------------------------------------------------------
__global__ __launch_bounds__(128) void k_layer2(const float* __restrict__ W2,
                                                const float* __restrict__ b1) {
    __shared__ float w2s[CH * COUT];  // 800
    __shared__ float b1s[CH];
    int tid = threadIdx.x;
    for (int i = tid; i < CH * COUT; i += 128) w2s[i] = W2[i];
    if (tid < CH) b1s[tid] = b1[tid];
    __syncthreads();

    int r = blockIdx.x * 128 + tid;
    if (r >= NN) return;
    float dv = g_dinv[r];

    float rv[CH];
#pragma unroll
    for (int q = 0; q < 10; q++) {
        float4 v = *(const float4*)&g_acc1[(size_t)r * CH + q * 4];
        rv[4 * q + 0] = fmaxf(dv * v.x + b1s[4 * q + 0], 0.f);
        rv[4 * q + 1] = fmaxf(dv * v.y + b1s[4 * q + 1], 0.f);
        rv[4 * q + 2] = fmaxf(dv * v.z + b1s[4 * q + 2], 0.f);
        rv[4 * q + 3] = fmaxf(dv * v.w + b1s[4 * q + 3], 0.f);
    }

    float acc[COUT];
#pragma unroll
    for (int c = 0; c < COUT; c++) acc[c] = 0.f;
#pragma unroll
    for (int k = 0; k < CH; k++) {
        float xv = rv[k];
#pragma unroll
        for (int c = 0; c < COUT; c++)
            acc[c] = fmaf(xv, w2s[k * COUT + c], acc[c]);
    }

#pragma unroll
    for (int q = 0; q < 5; q++) {
        float4 o = make_float4(dv * acc[4 * q + 0], dv * acc[4 * q + 1],
                               dv * acc[4 * q + 2], dv * acc[4 * q + 3]);
        *(float4*)&g_h2[(size_t)r * COUT + 4 * q] = o;
        *(float4*)&g_acc2[(size_t)r * COUT + 4 * q] = o;
    }
}

// ---------------------------------------------------------------------------
// Aggregation layer 2: 5 threads per edge
// ---------------------------------------------------------------------------
__global__ void k_agg2(const int* __restrict__ ei) {
    unsigned t = blockIdx.x * 256u + threadIdx.x;
    unsigned e = t / 5u;
    if (e >= (unsigned)NE) return;
    unsigned j = t - e * 5u;
    int s = ei[e];
    int d = ei[NE + e];
    float4 v = *(const float4*)&g_h2[(size_t)s * COUT + j * 4];
    red_add_v4(&g_acc2[(size_t)d * COUT + j * 4], v);
}

// ---------------------------------------------------------------------------
// Final: out = dinv * acc2 + b2
// ---------------------------------------------------------------------------
__global__ void k_final(float* __restrict__ out, const float* __restrict__ b2) {
    int idx = blockIdx.x * 256 + threadIdx.x;
    if (idx >= NN * COUT) return;
    int r = idx / COUT;
    int c = idx - r * COUT;
    out[idx] = g_dinv[r] * g_acc2[idx] + __ldg(&b2[c]);
}

// ---------------------------------------------------------------------------
extern "C" void kernel_launch(void* const* d_in, const int* in_sizes, int n_in,
                              void* d_out, int out_size) {
    const float* x  = (const float*)d_in[0];
    const int*   ei = (const int*)d_in[1];
    const float* W1 = (const float*)d_in[2];
    const float* b1 = (const float*)d_in[3];
    const float* W2 = (const float*)d_in[4];
    const float* b2 = (const float*)d_in[5];
    float* out = (float*)d_out;

    k_deg_init<<<(NN + 255) / 256, 256>>>();
    k_deg_count<<<(NE + 255) / 256, 256>>>(ei);
    k_dinv<<<(NN + 255) / 256, 256>>>();
    k_gemm1<<<(NN + 127) / 128, 128>>>(x, W1);
    {
        long long th = (long long)NE * 10;
        k_agg1<<<(unsigned)((th + 255) / 256), 256>>>(ei);
    }
    k_layer2<<<(NN + 127) / 128, 128>>>(W2, b1);
    {
        long long th = (long long)NE * 5;
        k_agg2<<<(unsigned)((th + 255) / 256), 256>>>(ei);
    }
    k_final<<<(NN * COUT + 255) / 256, 256>>>(out, b2);
}